// round 2
// baseline (speedup 1.0000x reference)
#include <cuda_runtime.h>
#include <cstdint>

// ---------------- problem constants ----------------
#define BB   16
#define CC   256
#define HH   64
#define WW   64
#define NHH  8
#define DHH  64
#define CIN  260
#define DQKV 512
#define HWN  4096               // H*W
#define PLEN 128                // W+H logits per query
#define SCALE 0.08838834764831843f  // 1/sqrt(128)

// ---------------- device scratch (global .bss, allowed) ----------------
// each tensor: B * DQKV * H * W floats = 33,554,432 (134 MB)
#define TSZ ((size_t)BB * DQKV * HWN)
__device__ float g_Q [TSZ];
__device__ float g_K [TSZ];
__device__ float g_V [TSZ];
__device__ float g_QT[TSZ];
__device__ float g_KT[TSZ];
__device__ float g_VT[TSZ];
__device__ float g_A [TSZ];
__device__ float g_AT[TSZ];
// logits/probs: B * NH * H * W * 128 = 67,108,864 floats (268 MB)
__device__ float g_P [(size_t)BB * NHH * HH * WW * PLEN];

// =====================================================================
// Kernel 1: QKV projection GEMM.  out[b][m][p] = sum_c W[m][c]*xp[b][c][p] + bias[m]
// xp = concat(x, pos_emb) along channels (CIN = 260).
// Tiles: BM=128, BN=128, BK=8. 256 threads, 8x8 microtile each.
// grid: (N/128=32, 12, 16); blockIdx.y: [0..3]->Q tiles, [4..7]->K, [8..11]->V
// =====================================================================
__global__ __launch_bounds__(256) void qkv_gemm(
    const float* __restrict__ x, const float* __restrict__ pos,
    const float* __restrict__ Wq, const float* __restrict__ bq,
    const float* __restrict__ Wk, const float* __restrict__ bk,
    const float* __restrict__ Wv, const float* __restrict__ bv)
{
    int which = blockIdx.y >> 2;
    int mBlk  = (blockIdx.y & 3) * 128;
    int nBlk  = blockIdx.x * 128;
    int b     = blockIdx.z;
    const float* Wt   = (which == 0) ? Wq : (which == 1) ? Wk : Wv;
    const float* bias = (which == 0) ? bq : (which == 1) ? bk : bv;
    float*       out  = (which == 0) ? g_Q : (which == 1) ? g_K : g_V;

    __shared__ float As[8][132];   // [k][m], padded
    __shared__ float Bs[8][128];   // [k][n]

    int t  = threadIdx.x;
    int tx = t & 15, ty = t >> 4;
    float acc[8][8] = {};
    const float* xb = x + (size_t)b * (CC * HWN);

    for (int k0 = 0; k0 < CIN; k0 += 8) {
        // load A tile (W): 128x8, guarded for K remainder (260 % 8 == 4)
        #pragma unroll
        for (int r = 0; r < 4; r++) {
            int idx = r * 256 + t;
            int m = idx >> 3, k = idx & 7;
            float v = 0.0f;
            if (k0 + k < CIN) v = Wt[(size_t)(mBlk + m) * CIN + (k0 + k)];
            As[k][m] = v;
        }
        // load B tile (xp): 8x128, one float4 per thread
        {
            int kk = t >> 5;
            int n  = (t & 31) * 4;
            int kg = k0 + kk;
            float4 v = make_float4(0.f, 0.f, 0.f, 0.f);
            if (kg < CC)
                v = *(const float4*)(xb + (size_t)kg * HWN + nBlk + n);
            else if (kg < CIN)
                v = *(const float4*)(pos + (size_t)(kg - CC) * HWN + nBlk + n);
            *(float4*)&Bs[kk][n] = v;
        }
        __syncthreads();
        #pragma unroll
        for (int kk = 0; kk < 8; kk++) {
            float4 a0 = *(float4*)&As[kk][ty * 8];
            float4 a1 = *(float4*)&As[kk][ty * 8 + 4];
            float4 b0 = *(float4*)&Bs[kk][tx * 8];
            float4 b1 = *(float4*)&Bs[kk][tx * 8 + 4];
            float av[8] = {a0.x, a0.y, a0.z, a0.w, a1.x, a1.y, a1.z, a1.w};
            float bv2[8] = {b0.x, b0.y, b0.z, b0.w, b1.x, b1.y, b1.z, b1.w};
            #pragma unroll
            for (int i = 0; i < 8; i++)
                #pragma unroll
                for (int j = 0; j < 8; j++)
                    acc[i][j] = fmaf(av[i], bv2[j], acc[i][j]);
        }
        __syncthreads();
    }

    float* ob = out + (size_t)b * (DQKV * HWN);
    #pragma unroll
    for (int i = 0; i < 8; i++) {
        int m = mBlk + ty * 8 + i;
        float bi = bias[m];
        float4 o0 = make_float4(acc[i][0] + bi, acc[i][1] + bi, acc[i][2] + bi, acc[i][3] + bi);
        float4 o1 = make_float4(acc[i][4] + bi, acc[i][5] + bi, acc[i][6] + bi, acc[i][7] + bi);
        *(float4*)(ob + (size_t)m * HWN + nBlk + tx * 8)     = o0;
        *(float4*)(ob + (size_t)m * HWN + nBlk + tx * 8 + 4) = o1;
    }
}

// =====================================================================
// Kernel 2: transpose each 64x64 image of Q,K,V -> QT,KT,VT
// grid: (B*DQKV = 8192, 3)
// =====================================================================
__global__ __launch_bounds__(256) void transpose3_kernel()
{
    const float* src = (blockIdx.y == 0) ? g_Q : (blockIdx.y == 1) ? g_K : g_V;
    float*       dst = (blockIdx.y == 0) ? g_QT : (blockIdx.y == 1) ? g_KT : g_VT;
    size_t base = (size_t)blockIdx.x * HWN;
    __shared__ float sm[64][65];
    int t = threadIdx.x;
    #pragma unroll
    for (int r = 0; r < 16; r++) {
        int idx = r * 256 + t;
        sm[idx >> 6][idx & 63] = src[base + idx];
    }
    __syncthreads();
    #pragma unroll
    for (int r = 0; r < 16; r++) {
        int idx = r * 256 + t;
        dst[base + idx] = sm[idx & 63][idx >> 6];
    }
}

// =====================================================================
// Kernel 3: row logits. block (i, h, b). S[j][k] = sum_d Q[d,i,j]*K[d,i,k]
// writes g_P[b,h,i,j, 0..63]
// =====================================================================
__global__ __launch_bounds__(256) void logits_row_kernel()
{
    int i = blockIdx.x, h = blockIdx.y, b = blockIdx.z;
    __shared__ float qs[64][64];
    __shared__ float ks[64][64];
    size_t base = ((size_t)(b * DQKV + h * DHH)) * HWN + i * WW;
    int t = threadIdx.x;
    #pragma unroll
    for (int r = 0; r < 16; r++) {
        int idx = r * 256 + t;
        int d = idx >> 6, j = idx & 63;
        qs[d][j] = g_Q[base + (size_t)d * HWN + j];
        ks[d][j] = g_K[base + (size_t)d * HWN + j];
    }
    __syncthreads();
    int tx = t & 15, ty = t >> 4;
    float acc[4][4] = {};
    #pragma unroll
    for (int d = 0; d < 64; d++) {
        float4 q4 = *(float4*)&qs[d][ty * 4];
        float4 k4 = *(float4*)&ks[d][tx * 4];
        float qa[4] = {q4.x, q4.y, q4.z, q4.w};
        float ka[4] = {k4.x, k4.y, k4.z, k4.w};
        #pragma unroll
        for (int u = 0; u < 4; u++)
            #pragma unroll
            for (int v = 0; v < 4; v++)
                acc[u][v] = fmaf(qa[u], ka[v], acc[u][v]);
    }
    size_t pbase = (((size_t)((b * NHH + h) * HH + i)) * WW) * PLEN;
    #pragma unroll
    for (int u = 0; u < 4; u++) {
        int j = ty * 4 + u;
        float4 o = make_float4(acc[u][0] * SCALE, acc[u][1] * SCALE,
                               acc[u][2] * SCALE, acc[u][3] * SCALE);
        *(float4*)&g_P[pbase + (size_t)j * PLEN + tx * 4] = o;
    }
}

// =====================================================================
// Kernel 4: column logits. block (j, h, b). L[i][k] = sum_d Q[d,i,j]*K[d,k,j]
// reads QT/KT rows (contiguous), writes g_P[b,h,i,j, 64..127]
// =====================================================================
__global__ __launch_bounds__(256) void logits_col_kernel()
{
    int j = blockIdx.x, h = blockIdx.y, b = blockIdx.z;
    __shared__ float qs[64][64];   // qs[d][i] = Q[d,i,j]
    __shared__ float ks[64][64];   // ks[d][k] = K[d,k,j]
    size_t base = ((size_t)(b * DQKV + h * DHH)) * HWN + j * HH;
    int t = threadIdx.x;
    #pragma unroll
    for (int r = 0; r < 16; r++) {
        int idx = r * 256 + t;
        int d = idx >> 6, ii = idx & 63;
        qs[d][ii] = g_QT[base + (size_t)d * HWN + ii];
        ks[d][ii] = g_KT[base + (size_t)d * HWN + ii];
    }
    __syncthreads();
    int tx = t & 15, ty = t >> 4;
    float acc[4][4] = {};
    #pragma unroll
    for (int d = 0; d < 64; d++) {
        float4 q4 = *(float4*)&qs[d][ty * 4];
        float4 k4 = *(float4*)&ks[d][tx * 4];
        float qa[4] = {q4.x, q4.y, q4.z, q4.w};
        float ka[4] = {k4.x, k4.y, k4.z, k4.w};
        #pragma unroll
        for (int u = 0; u < 4; u++)
            #pragma unroll
            for (int v = 0; v < 4; v++)
                acc[u][v] = fmaf(qa[u], ka[v], acc[u][v]);
    }
    size_t pre = ((size_t)((b * NHH + h) * HH) * WW + j) * PLEN + 64;
    #pragma unroll
    for (int u = 0; u < 4; u++) {
        int i = ty * 4 + u;
        float4 o = make_float4(acc[u][0] * SCALE, acc[u][1] * SCALE,
                               acc[u][2] * SCALE, acc[u][3] * SCALE);
        *(float4*)&g_P[pre + (size_t)i * (WW * PLEN) + tx * 4] = o;
    }
}

// =====================================================================
// Kernel 5: softmax over 128 logits per query, in place. 1 warp per row.
// rows = B*NH*H*W = 524288; grid 65536 x 256 threads (8 warps)
// =====================================================================
__global__ __launch_bounds__(256) void softmax_kernel()
{
    size_t row = (size_t)blockIdx.x * 8 + (threadIdx.x >> 5);
    int lane = threadIdx.x & 31;
    float* p = g_P + row * PLEN + lane * 4;
    float4 v = *(float4*)p;
    float m = fmaxf(fmaxf(v.x, v.y), fmaxf(v.z, v.w));
    #pragma unroll
    for (int o = 16; o; o >>= 1) m = fmaxf(m, __shfl_xor_sync(0xffffffffu, m, o));
    v.x = __expf(v.x - m); v.y = __expf(v.y - m);
    v.z = __expf(v.z - m); v.w = __expf(v.w - m);
    float s = v.x + v.y + v.z + v.w;
    #pragma unroll
    for (int o = 16; o; o >>= 1) s += __shfl_xor_sync(0xffffffffu, s, o);
    float inv = 1.0f / s;
    v.x *= inv; v.y *= inv; v.z *= inv; v.w *= inv;
    *(float4*)p = v;
}

// =====================================================================
// Kernel 6: row attention. block (i,h,b): a_w[d][j] = sum_k p_w[j][k]*V[d][i][k]
// writes g_A
// =====================================================================
__global__ __launch_bounds__(256) void attn_row_kernel()
{
    int i = blockIdx.x, h = blockIdx.y, b = blockIdx.z;
    __shared__ float vsT[64][68];  // [k][d]
    __shared__ float psT[64][68];  // [k][j]
    size_t vbase = ((size_t)(b * DQKV + h * DHH)) * HWN + i * WW;
    size_t pbase = (((size_t)((b * NHH + h) * HH + i)) * WW) * PLEN;
    int t = threadIdx.x;
    #pragma unroll
    for (int r = 0; r < 16; r++) {
        int idx = r * 256 + t;
        int a = idx >> 6, k = idx & 63;
        vsT[k][a] = g_V[vbase + (size_t)a * HWN + k];         // a = d
        psT[k][a] = g_P[pbase + (size_t)a * PLEN + k];        // a = j (first 64 = p_w)
    }
    __syncthreads();
    int tx = t & 15, ty = t >> 4;
    float acc[4][4] = {};
    #pragma unroll
    for (int k = 0; k < 64; k++) {
        float4 v4 = *(float4*)&vsT[k][ty * 4];
        float4 p4 = *(float4*)&psT[k][tx * 4];
        float va[4] = {v4.x, v4.y, v4.z, v4.w};
        float pa[4] = {p4.x, p4.y, p4.z, p4.w};
        #pragma unroll
        for (int u = 0; u < 4; u++)
            #pragma unroll
            for (int v = 0; v < 4; v++)
                acc[u][v] = fmaf(va[u], pa[v], acc[u][v]);
    }
    #pragma unroll
    for (int u = 0; u < 4; u++) {
        int d = ty * 4 + u;
        float4 o = make_float4(acc[u][0], acc[u][1], acc[u][2], acc[u][3]);
        *(float4*)&g_A[vbase + (size_t)d * HWN + tx * 4] = o;
    }
}

// =====================================================================
// Kernel 7: column attention. block (j,h,b): a_h[d][i] = sum_k p_h[i][k]*V[d][k][j]
// reads VT rows, writes g_AT (transposed layout)
// =====================================================================
__global__ __launch_bounds__(256) void attn_col_kernel()
{
    int j = blockIdx.x, h = blockIdx.y, b = blockIdx.z;
    __shared__ float vsT[64][68];  // [k][d] = V[d,k,j]
    __shared__ float psT[64][68];  // [k][i]
    size_t vbase = ((size_t)(b * DQKV + h * DHH)) * HWN + j * HH;
    size_t pcol  = ((size_t)((b * NHH + h) * HH) * WW + j) * PLEN + 64;
    int t = threadIdx.x;
    #pragma unroll
    for (int r = 0; r < 16; r++) {
        int idx = r * 256 + t;
        int a = idx >> 6, k = idx & 63;
        vsT[k][a] = g_VT[vbase + (size_t)a * HWN + k];               // a = d
        psT[k][a] = g_P[pcol + (size_t)a * (WW * PLEN) + k];         // a = i
    }
    __syncthreads();
    int tx = t & 15, ty = t >> 4;
    float acc[4][4] = {};
    #pragma unroll
    for (int k = 0; k < 64; k++) {
        float4 v4 = *(float4*)&vsT[k][ty * 4];
        float4 p4 = *(float4*)&psT[k][tx * 4];
        float va[4] = {v4.x, v4.y, v4.z, v4.w};
        float pa[4] = {p4.x, p4.y, p4.z, p4.w};
        #pragma unroll
        for (int u = 0; u < 4; u++)
            #pragma unroll
            for (int v = 0; v < 4; v++)
                acc[u][v] = fmaf(va[u], pa[v], acc[u][v]);
    }
    #pragma unroll
    for (int u = 0; u < 4; u++) {
        int d = ty * 4 + u;
        float4 o = make_float4(acc[u][0], acc[u][1], acc[u][2], acc[u][3]);
        *(float4*)&g_AT[vbase + (size_t)d * HWN + tx * 4] = o;   // AT[ch][j][i]
    }
}

// =====================================================================
// Kernel 8: A[i][j] += AT[j][i] per (b,ch) image. grid 8192.
// =====================================================================
__global__ __launch_bounds__(256) void transpose_add_kernel()
{
    size_t base = (size_t)blockIdx.x * HWN;
    __shared__ float sm[64][65];
    int t = threadIdx.x;
    #pragma unroll
    for (int r = 0; r < 16; r++) {
        int idx = r * 256 + t;
        sm[idx >> 6][idx & 63] = g_AT[base + idx];
    }
    __syncthreads();
    #pragma unroll
    for (int r = 0; r < 16; r++) {
        int idx = r * 256 + t;
        g_A[base + idx] += sm[idx & 63][idx >> 6];
    }
}

// =====================================================================
// Kernel 9: output projection + residual.
// out[b][m][p] = x[b][m][p] + sum_c Wo[m][c]*A[b][c][p] + bo[m]
// M=256 (2 tiles), K=512, N=4096 per batch.
// =====================================================================
__global__ __launch_bounds__(256) void proj_gemm(
    const float* __restrict__ x, const float* __restrict__ Wo,
    const float* __restrict__ bo, float* __restrict__ out)
{
    int mBlk = blockIdx.y * 128;
    int nBlk = blockIdx.x * 128;
    int b    = blockIdx.z;

    __shared__ float As[8][132];
    __shared__ float Bs[8][128];

    int t  = threadIdx.x;
    int tx = t & 15, ty = t >> 4;
    float acc[8][8] = {};
    const float* Ab = g_A + (size_t)b * (DQKV * HWN);

    for (int k0 = 0; k0 < DQKV; k0 += 8) {
        #pragma unroll
        for (int r = 0; r < 4; r++) {
            int idx = r * 256 + t;
            int m = idx >> 3, k = idx & 7;
            As[k][m] = Wo[(size_t)(mBlk + m) * DQKV + k0 + k];
        }
        {
            int kk = t >> 5;
            int n  = (t & 31) * 4;
            *(float4*)&Bs[kk][n] =
                *(const float4*)(Ab + (size_t)(k0 + kk) * HWN + nBlk + n);
        }
        __syncthreads();
        #pragma unroll
        for (int kk = 0; kk < 8; kk++) {
            float4 a0 = *(float4*)&As[kk][ty * 8];
            float4 a1 = *(float4*)&As[kk][ty * 8 + 4];
            float4 b0 = *(float4*)&Bs[kk][tx * 8];
            float4 b1 = *(float4*)&Bs[kk][tx * 8 + 4];
            float av[8] = {a0.x, a0.y, a0.z, a0.w, a1.x, a1.y, a1.z, a1.w};
            float bv2[8] = {b0.x, b0.y, b0.z, b0.w, b1.x, b1.y, b1.z, b1.w};
            #pragma unroll
            for (int i = 0; i < 8; i++)
                #pragma unroll
                for (int j = 0; j < 8; j++)
                    acc[i][j] = fmaf(av[i], bv2[j], acc[i][j]);
        }
        __syncthreads();
    }

    #pragma unroll
    for (int i = 0; i < 8; i++) {
        int m = mBlk + ty * 8 + i;
        float bi = bo[m];
        size_t oidx = ((size_t)(b * CC + m)) * HWN + nBlk + tx * 8;
        float4 x0 = *(const float4*)(x + oidx);
        float4 x1 = *(const float4*)(x + oidx + 4);
        float4 o0 = make_float4(acc[i][0] + bi + x0.x, acc[i][1] + bi + x0.y,
                                acc[i][2] + bi + x0.z, acc[i][3] + bi + x0.w);
        float4 o1 = make_float4(acc[i][4] + bi + x1.x, acc[i][5] + bi + x1.y,
                                acc[i][6] + bi + x1.z, acc[i][7] + bi + x1.w);
        *(float4*)(out + oidx)     = o0;
        *(float4*)(out + oidx + 4) = o1;
    }
}

// =====================================================================
extern "C" void kernel_launch(void* const* d_in, const int* in_sizes, int n_in,
                              void* d_out, int out_size)
{
    const float* x   = (const float*)d_in[0];
    const float* pos = (const float*)d_in[1];
    const float* Wk  = (const float*)d_in[2];
    const float* bk  = (const float*)d_in[3];
    const float* Wq  = (const float*)d_in[4];
    const float* bq  = (const float*)d_in[5];
    const float* Wv  = (const float*)d_in[6];
    const float* bv  = (const float*)d_in[7];
    const float* Wo  = (const float*)d_in[8];
    const float* bo  = (const float*)d_in[9];
    float* out = (float*)d_out;

    qkv_gemm<<<dim3(32, 12, BB), 256>>>(x, pos, Wq, bq, Wk, bk, Wv, bv);
    transpose3_kernel<<<dim3(BB * DQKV, 3), 256>>>();
    logits_row_kernel<<<dim3(HH, NHH, BB), 256>>>();
    logits_col_kernel<<<dim3(WW, NHH, BB), 256>>>();
    softmax_kernel<<<65536, 256>>>();
    attn_row_kernel<<<dim3(HH, NHH, BB), 256>>>();
    attn_col_kernel<<<dim3(WW, NHH, BB), 256>>>();
    transpose_add_kernel<<<BB * DQKV, 256>>>();
    proj_gemm<<<dim3(32, 2, BB), 256>>>(x, Wo, bo, out);
}